// round 9
// baseline (speedup 1.0000x reference)
#include <cuda_runtime.h>
#include <cuda_bf16.h>
#include <math.h>
#include <stdint.h>

// Problem constants
#define EB 1024     // embed dim
#define DH 64       // head dim
#define NH 16       // heads
#define BB 8
#define LL 4096
#define MT (BB*LL)          // 32768 tokens
#define GNP 2176            // padded N (17 tiles of 128)
#define GK EB

// ---------------- scratch ----------------
__device__ float g_a [ (size_t)MT * EB ];
__device__ float g_b [ (size_t)MT * EB ];
__device__ float g_hs[ (size_t)MT * EB ];
__device__ float g_dx[ (size_t)MT * DH ];
__device__ float g_wt[ (size_t)GNP * GK ];  // weights [n][k], tf32-rounded
__device__ float g_et[ (size_t)MT * GK ];   // emb, tf32-rounded

#define SCH 32
#define SCL (LL / SCH)      // 128
__device__ float g_cp[128 * SCH * 64];
__device__ float g_cq[128 * SCH * 64];

// ---------------- helpers ----------------
__device__ __forceinline__ uint32_t smem_u32(const void* p) {
    uint32_t r;
    asm("{ .reg .u64 t; cvta.to.shared.u64 t, %1; cvt.u32.u64 %0, t; }" : "=r"(r) : "l"(p));
    return r;
}
__device__ __forceinline__ void cp_async16(uint32_t dst, const void* src) {
    asm volatile("cp.async.cg.shared.global [%0], [%1], 16;" :: "r"(dst), "l"(src) : "memory");
}
__device__ __forceinline__ void cp_commit() {
    asm volatile("cp.async.commit_group;" ::: "memory");
}
__device__ __forceinline__ uint32_t tf32u(float x) {
    uint32_t u;
    asm("cvt.rna.tf32.f32 %0, %1;" : "=r"(u) : "f"(x));
    return u;
}
__device__ __forceinline__ void mma_tf32(float* c,
                                         uint32_t a0, uint32_t a1, uint32_t a2, uint32_t a3,
                                         uint32_t b0, uint32_t b1) {
    asm volatile(
        "mma.sync.aligned.m16n8k8.row.col.f32.tf32.tf32.f32 "
        "{%0,%1,%2,%3}, {%4,%5,%6,%7}, {%8,%9}, {%0,%1,%2,%3};"
        : "+f"(c[0]), "+f"(c[1]), "+f"(c[2]), "+f"(c[3])
        : "r"(a0), "r"(a1), "r"(a2), "r"(a3), "r"(b0), "r"(b1));
}
__device__ __forceinline__ float tanh_fast(float x) {
    float xc = fminf(fmaxf(x, -10.f), 10.f);
    float t  = __expf(2.f * xc);
    return __fdividef(t - 1.f, t + 1.f);
}

// ---------------- launch 0: pre-round emb to tf32 ----------------
__global__ void preround_kernel(const float* __restrict__ emb)
{
    size_t i = ((size_t)blockIdx.x * 256 + threadIdx.x) * 4;
    float4 x = *(const float4*)(emb + i);
    float4 y;
    y.x = __uint_as_float(tf32u(x.x));
    y.y = __uint_as_float(tf32u(x.y));
    y.z = __uint_as_float(tf32u(x.z));
    y.w = __uint_as_float(tf32u(x.w));
    *(float4*)(g_et + i) = y;
}

// ---------------- launches 1,2: pack weights [n][k] ----------------
__global__ void pack_a_kernel(const float* __restrict__ Wa)
{
    size_t idx = (size_t)blockIdx.x * 256 + threadIdx.x;   // < 1024*1024
    int n = (int)(idx >> 10);
    int k = (int)(idx & 1023);
    float v = Wa[(size_t)(n >> 6) * (EB * DH) + (size_t)k * DH + (n & 63)];
    g_wt[idx] = __uint_as_float(tf32u(v));
}
__global__ void pack_bd_kernel(const float* __restrict__ Wb, const float* __restrict__ Wd)
{
    size_t idx = (size_t)blockIdx.x * 256 + threadIdx.x;   // < 1152*1024
    int n = (int)(idx >> 10);
    int k = (int)(idx & 1023);
    float v;
    if (n < 1024) {
        v = Wb[(size_t)(n >> 6) * (EB * DH) + (size_t)k * DH + (n & 63)];
    } else {
        int n2 = n - 1024;
        v = (n2 < 64) ? Wd[(size_t)k * DH + n2] : 0.f;
    }
    g_wt[(size_t)(1024 + n) * 1024 + k] = __uint_as_float(tf32u(v));
}

// ---------------- launch 3: TF32 gates GEMM, CTA 256x128, warp 64x64 ----------------
#define KC 32
#define NKC (GK / KC)           // 32
#define ROWB 128
#define ATILEB (256 * ROWB)     // 32768
#define BTILEB (128 * ROWB)     // 16384
#define STAGEB (ATILEB + BTILEB)// 49152
#define GEMM_SMEM (3 * STAGEB)  // 147456

#define SWZ(row, chunk) ((uint32_t)((row) * ROWB + ((((chunk) ^ (((row) & 1) << 2))) << 4)))

__device__ __forceinline__ void gemm_load_stage(uint32_t sst, int kc, int tid,
                                                const char* Ag, const char* Bg)
{
    const size_t kb = (size_t)kc * 128;
#pragma unroll
    for (int j = 0; j < 8; j++) {          // A: 256 rows
        int id  = tid + j * 256;           // 0..2047
        int row = id >> 3;
        int c   = id & 7;
        cp_async16(sst + SWZ(row, c), Ag + (size_t)row * 4096 + kb + c * 16);
    }
#pragma unroll
    for (int j = 0; j < 4; j++) {          // B: 128 rows
        int id  = tid + j * 256;           // 0..1023
        int row = id >> 3;
        int c   = id & 7;
        cp_async16(sst + ATILEB + SWZ(row, c), Bg + (size_t)row * 4096 + kb + c * 16);
    }
}

__global__ void __launch_bounds__(256, 1)
gemm_tf32_kernel(const float* __restrict__ ba,
                 const float* __restrict__ bb,
                 const float* __restrict__ bd)
{
    extern __shared__ char sm_raw[];
    const int tid  = threadIdx.x;
    const int wid  = tid >> 5;
    const int lane = tid & 31;
    const uint32_t sbase = smem_u32(sm_raw);

    const long m0 = (long)blockIdx.y * 256;
    const int  n0 = blockIdx.x * 128;
    const int  wm = (wid & 3) * 64;      // 4 warps in M
    const int  wn = (wid >> 2) * 64;     // 2 warps in N

    const char* Ag = (const char*)(g_et + (size_t)m0 * GK);
    const char* Bg = (const char*)(g_wt + (size_t)n0 * GK);

    float acc[4][8][4];
#pragma unroll
    for (int i = 0; i < 4; i++)
#pragma unroll
        for (int j = 0; j < 8; j++)
#pragma unroll
            for (int q = 0; q < 4; q++) acc[i][j][q] = 0.f;

    gemm_load_stage(sbase, 0, tid, Ag, Bg);
    cp_commit();
    gemm_load_stage(sbase + STAGEB, 1, tid, Ag, Bg);
    cp_commit();

    const int lrow4 = lane >> 2;
    const int lch   = lane & 3;

    int stage = 0;
    for (int kc = 0; kc < NKC; kc++) {
        if (kc + 1 < NKC) {
            asm volatile("cp.async.wait_group 1;" ::: "memory");
        } else {
            asm volatile("cp.async.wait_group 0;" ::: "memory");
        }
        __syncthreads();
        if (kc + 2 < NKC) {
            int nstage = stage + 2; if (nstage >= 3) nstage -= 3;
            gemm_load_stage(sbase + nstage * STAGEB, kc + 2, tid, Ag, Bg);
            cp_commit();
        }

        const char* sA = sm_raw + stage * STAGEB;
        const char* sB = sA + ATILEB;

#pragma unroll
        for (int k16 = 0; k16 < 2; k16++) {
            const int ch = k16 * 4 + lch;
            uint32_t aw[4][2][4];
#pragma unroll
            for (int mt = 0; mt < 4; mt++) {
#pragma unroll
                for (int hh = 0; hh < 2; hh++) {
                    int row = wm + mt * 16 + hh * 8 + lrow4;
                    const uint4 v = *(const uint4*)(sA + SWZ(row, ch));
                    aw[mt][hh][0] = v.x;
                    aw[mt][hh][1] = v.y;
                    aw[mt][hh][2] = v.z;
                    aw[mt][hh][3] = v.w;
                }
            }
#pragma unroll
            for (int g = 0; g < 8; g++) {
                int row = wn + g * 8 + lrow4;
                const uint4 bv = *(const uint4*)(sB + SWZ(row, ch));
#pragma unroll
                for (int mt = 0; mt < 4; mt++) {
                    mma_tf32(acc[mt][g], aw[mt][0][0], aw[mt][1][0], aw[mt][0][1], aw[mt][1][1], bv.x, bv.y);
                    mma_tf32(acc[mt][g], aw[mt][0][2], aw[mt][1][2], aw[mt][0][3], aw[mt][1][3], bv.z, bv.w);
                }
            }
        }
        stage++; if (stage == 3) stage = 0;
    }
    __syncthreads();

    // ---- epilogue: stage 256x128 D in smem (stride 132), coalesced write ----
    float* sD = (float*)sm_raw;
#pragma unroll
    for (int mt = 0; mt < 4; mt++) {
#pragma unroll
        for (int g = 0; g < 8; g++) {
            int ml = wm + mt * 16 + (lane >> 2);
            int nl = wn + g * 8 + (lane & 3) * 2;
            *(float2*)&sD[ml * 132 + nl]       = make_float2(acc[mt][g][0], acc[mt][g][1]);
            *(float2*)&sD[(ml + 8) * 132 + nl] = make_float2(acc[mt][g][2], acc[mt][g][3]);
        }
    }
    __syncthreads();

    for (int i = tid; i < 256 * 128; i += 256) {
        int mm = i >> 7;
        int nn = i & 127;
        int ng = n0 + nn;
        float c = sD[mm * 132 + nn];
        long m = m0 + mm;
        if (ng < 1024) {
            g_a[m * EB + ng] = tanh_fast(c + ba[ng]);
        } else if (ng < 2048) {
            g_b[m * EB + (ng - 1024)] = c + bb[ng - 1024];
        } else if (ng < 2112) {
            g_dx[m * DH + (ng - 2048)] = c + bd[ng - 2048];
        }
    }
}

// ---------------- chunked scan ----------------
__global__ void __launch_bounds__(1024)
scanA_kernel()
{
    const int b = blockIdx.x >> 5;
    const int c = blockIdx.x & 31;
    const int e = threadIdx.x;
    size_t base = ((size_t)b * LL + (size_t)c * SCL) * EB + e;
    float P = 1.f, Q = 0.f;
#pragma unroll 8
    for (int l = 0; l < SCL; l++) {
        size_t idx = base + (size_t)l * EB;
        float av = g_a[idx];
        float bv = g_b[idx];
        Q = fmaf(av, Q, bv);
        P *= av;
    }
    int bh = b * 16 + (e >> 6);
    g_cp[(bh * SCH + c) * 64 + (e & 63)] = P;
    g_cq[(bh * SCH + c) * 64 + (e & 63)] = Q;
}

__global__ void __launch_bounds__(1024)
scanC_kernel()
{
    const int b = blockIdx.x >> 5;
    const int c = blockIdx.x & 31;
    const int e = threadIdx.x;
    const int bh = b * 16 + (e >> 6);
    const int d  = e & 63;
    float hv = 0.f;
    for (int cc = 0; cc < c; cc++) {
        int i = (bh * SCH + cc) * 64 + d;
        hv = fmaf(g_cp[i], hv, g_cq[i]);
    }
    size_t base = ((size_t)b * LL + (size_t)c * SCL) * EB + e;
#pragma unroll 8
    for (int l = 0; l < SCL; l++) {
        size_t idx = base + (size_t)l * EB;
        float av = g_a[idx];
        float bv = g_b[idx];
        hv = fmaf(av, hv, bv);
        g_hs[idx] = hv;
    }
}

// ---------------- fused per-token epilogue ----------------
#define TOK 64
#define HS_STRIDE 68
#define POST_FLOATS 21248
#define POST_BYTES  (POST_FLOATS * 4)

__device__ __forceinline__ float grp8_sum(float v) {
    v += __shfl_xor_sync(0xffffffffu, v, 1);
    v += __shfl_xor_sync(0xffffffffu, v, 2);
    v += __shfl_xor_sync(0xffffffffu, v, 4);
    return v;
}

__device__ __forceinline__ void post_prefetch(uint32_t swc, uint32_t shs,
                                              const float* __restrict__ Wc,
                                              int h, long token0, int tid)
{
    const char* wsrc = (const char*)(Wc + (size_t)h * 4096);
#pragma unroll
    for (int i = 0; i < 4; i++) {
        int idx = tid + i * 256;
        cp_async16(swc + idx * 16, wsrc + idx * 16);
    }
#pragma unroll
    for (int i = 0; i < 4; i++) {
        int idx = tid + i * 256;
        int t = idx >> 4;
        int c = idx & 15;
        const char* hsrc = (const char*)(g_hs + (token0 + t) * (size_t)EB + h * 64);
        cp_async16(shs + (uint32_t)(t * HS_STRIDE * 4 + c * 16), hsrc + c * 16);
    }
}

__global__ void __launch_bounds__(256)
post_kernel(const float* __restrict__ Wc,  const float* __restrict__ bc,
            const float* __restrict__ head_w,
            const float* __restrict__ hn_g, const float* __restrict__ hn_b,
            const float* __restrict__ W1,  const float* __restrict__ b1,
            const float* __restrict__ W2,  const float* __restrict__ b2,
            const float* __restrict__ Wp,  const float* __restrict__ bp,
            const float* __restrict__ ng,  const float* __restrict__ nb,
            float* __restrict__ out)
{
    extern __shared__ float sm[];
    const int tid = threadIdx.x;
    const int tt  = tid >> 3;
    const int eg  = tid & 7;
    const int e0  = eg * 8;
    const long token0 = (long)blockIdx.x * TOK;
    const long tok0 = token0 + tt;
    const long tok1 = token0 + tt + 32;

    const uint32_t swc_u0 = smem_u32(sm);
    const uint32_t swc_u1 = smem_u32(sm + 4096);
    const uint32_t shs_u0 = smem_u32(sm + 8192);
    const uint32_t shs_u1 = smem_u32(sm + 8192 + TOK * HS_STRIDE);

    float dxv0[8], dxv1[8], acc0[8], acc1[8];
#pragma unroll
    for (int k = 0; k < 8; k++) {
        dxv0[k] = g_dx[tok0 * DH + e0 + k];
        dxv1[k] = g_dx[tok1 * DH + e0 + k];
        acc0[k] = dxv0[k];
        acc1[k] = dxv1[k];
    }

    post_prefetch(swc_u0, shs_u0, Wc, 0, token0, tid);
    cp_commit();

    for (int h = 0; h < NH; h++) {
        const int cur = h & 1;
        if (h + 1 < NH) {
            post_prefetch(cur ? swc_u0 : swc_u1, cur ? shs_u0 : shs_u1, Wc, h + 1, token0, tid);
            cp_commit();
            asm volatile("cp.async.wait_group 1;" ::: "memory");
        } else {
            asm volatile("cp.async.wait_group 0;" ::: "memory");
        }
        __syncthreads();

        const float* sWc = sm + (cur ? 4096 : 0);
        const float* sHs = sm + 8192 + (cur ? TOK * HS_STRIDE : 0);

        float o0[8], o1[8];
#pragma unroll
        for (int k = 0; k < 8; k++) {
            float bck = bc[h * DH + e0 + k];
            o0[k] = bck + dxv0[k];
            o1[k] = bck + dxv1[k];
        }
#pragma unroll 8
        for (int d = 0; d < 64; d++) {
            float hv0 = sHs[tt * HS_STRIDE + d];
            float hv1 = sHs[(tt + 32) * HS_STRIDE + d];
            float4 w0 = *(const float4*)&sWc[d * 64 + e0];
            float4 w1 = *(const float4*)&sWc[d * 64 + e0 + 4];
            o0[0] = fmaf(hv0, w0.x, o0[0]); o0[1] = fmaf(hv0, w0.y, o0[1]);
            o0[2] = fmaf(hv0, w0.z, o0[2]); o0[3] = fmaf(hv0, w0.w, o0[3]);
            o0[4] = fmaf(hv0, w1.x, o0[4]); o0[5] = fmaf(hv0, w1.y, o0[5]);
            o0[6] = fmaf(hv0, w1.z, o0[6]); o0[7] = fmaf(hv0, w1.w, o0[7]);
            o1[0] = fmaf(hv1, w0.x, o1[0]); o1[1] = fmaf(hv1, w0.y, o1[1]);
            o1[2] = fmaf(hv1, w0.z, o1[2]); o1[3] = fmaf(hv1, w0.w, o1[3]);
            o1[4] = fmaf(hv1, w1.x, o1[4]); o1[5] = fmaf(hv1, w1.y, o1[5]);
            o1[6] = fmaf(hv1, w1.z, o1[6]); o1[7] = fmaf(hv1, w1.w, o1[7]);
        }
        float s10 = 0.f, s20 = 0.f, s11 = 0.f, s21 = 0.f;
#pragma unroll
        for (int k = 0; k < 8; k++) {
            s10 += o0[k]; s20 += o0[k] * o0[k];
            s11 += o1[k]; s21 += o1[k] * o1[k];
        }
        s10 = grp8_sum(s10); s20 = grp8_sum(s20);
        s11 = grp8_sum(s11); s21 = grp8_sum(s21);
        float mean0 = s10 * (1.f / 64.f);
        float var0  = s20 * (1.f / 64.f) - mean0 * mean0;
        float rstd0 = rsqrtf(var0 + 1e-5f);
        float mean1 = s11 * (1.f / 64.f);
        float var1  = s21 * (1.f / 64.f) - mean1 * mean1;
        float rstd1 = rsqrtf(var1 + 1e-5f);
        float hw = head_w[h];
#pragma unroll
        for (int k = 0; k < 8; k++) {
            float gk = hn_g[h * DH + e0 + k];
            float bk = hn_b[h * DH + e0 + k];
            acc0[k] = fmaf(hw, (o0[k] - mean0) * rstd0 * gk + bk, acc0[k]);
            acc1[k] = fmaf(hw, (o1[k] - mean1) * rstd1 * gk + bk, acc1[k]);
        }
        __syncthreads();
    }

    float u0[8], u1[8];
    {
        float s10 = 0.f, s20 = 0.f, s11 = 0.f, s21 = 0.f;
#pragma unroll
        for (int k = 0; k < 8; k++) {
            acc0[k] *= (1.f / (float)NH);
            acc1[k] *= (1.f / (float)NH);
            s10 += acc0[k]; s20 += acc0[k] * acc0[k];
            s11 += acc1[k]; s21 += acc1[k] * acc1[k];
        }
        s10 = grp8_sum(s10); s20 = grp8_sum(s20);
        s11 = grp8_sum(s11); s21 = grp8_sum(s21);
        float mean0 = s10 * (1.f / 64.f);
        float var0  = s20 * (1.f / 64.f) - mean0 * mean0;
        float rstd0 = rsqrtf(var0 + 1e-5f);
        float mean1 = s11 * (1.f / 64.f);
        float var1  = s21 * (1.f / 64.f) - mean1 * mean1;
        float rstd1 = rsqrtf(var1 + 1e-5f);
#pragma unroll
        for (int k = 0; k < 8; k++) {
            float ngk = ng[e0 + k], nbk = nb[e0 + k];
            u0[k] = acc0[k] + (acc0[k] - mean0) * rstd0 * ngk + nbk;
            u1[k] = acc1[k] + (acc1[k] - mean1) * rstd1 * ngk + nbk;
        }
    }

    __syncthreads();

    float* sW1c = sm;
    float* sW2c = sm + 4096;
    float* sU   = sm + 8192;
    float* sGc  = sm + 8192 + TOK * HS_STRIDE;
    float* sHo  = sm + 8192 + 2 * TOK * HS_STRIDE;

#pragma unroll
    for (int k = 0; k < 8; k++) {
        sU[tt * HS_STRIDE + e0 + k]        = u0[k];
        sU[(tt + 32) * HS_STRIDE + e0 + k] = u1[k];
    }

    float o20[8], o21[8];
#pragma unroll
    for (int k = 0; k < 8; k++) { o20[k] = b2[e0 + k]; o21[k] = o20[k]; }

    for (int jc = 0; jc < 4; jc++) {
        __syncthreads();
#pragma unroll
        for (int i = 0; i < 16; i++) {
            int idx = tid + i * 256;
            int d = idx >> 6, jj = idx & 63;
            sW1c[idx] = W1[d * 256 + jc * 64 + jj];
            sW2c[idx] = W2[(jc * 64 + (idx >> 6)) * 64 + (idx & 63)];
        }
        __syncthreads();
#pragma unroll
        for (int kk = 0; kk < 8; kk++) {
            int jl = eg + 8 * kk;
            float m0 = b1[jc * 64 + jl], m1 = m0;
#pragma unroll 8
            for (int d = 0; d < 64; d++) {
                float w = sW1c[d * 64 + jl];
                m0 = fmaf(sU[tt * HS_STRIDE + d], w, m0);
                m1 = fmaf(sU[(tt + 32) * HS_STRIDE + d], w, m1);
            }
            sGc[tt * HS_STRIDE + jl]        = 0.5f * m0 * (1.f + erff(m0 * 0.70710678118654752f));
            sGc[(tt + 32) * HS_STRIDE + jl] = 0.5f * m1 * (1.f + erff(m1 * 0.70710678118654752f));
        }
        __syncthreads();
#pragma unroll 8
        for (int jj = 0; jj < 64; jj++) {
            float gv0 = sGc[tt * HS_STRIDE + jj];
            float gv1 = sGc[(tt + 32) * HS_STRIDE + jj];
            float4 w0 = *(const float4*)&sW2c[jj * 64 + e0];
            float4 w1 = *(const float4*)&sW2c[jj * 64 + e0 + 4];
            o20[0] = fmaf(gv0, w0.x, o20[0]); o20[1] = fmaf(gv0, w0.y, o20[1]);
            o20[2] = fmaf(gv0, w0.z, o20[2]); o20[3] = fmaf(gv0, w0.w, o20[3]);
            o20[4] = fmaf(gv0, w1.x, o20[4]); o20[5] = fmaf(gv0, w1.y, o20[5]);
            o20[6] = fmaf(gv0, w1.z, o20[6]); o20[7] = fmaf(gv0, w1.w, o20[7]);
            o21[0] = fmaf(gv1, w0.x, o21[0]); o21[1] = fmaf(gv1, w0.y, o21[1]);
            o21[2] = fmaf(gv1, w0.z, o21[2]); o21[3] = fmaf(gv1, w0.w, o21[3]);
            o21[4] = fmaf(gv1, w1.x, o21[4]); o21[5] = fmaf(gv1, w1.y, o21[5]);
            o21[6] = fmaf(gv1, w1.z, o21[6]); o21[7] = fmaf(gv1, w1.w, o21[7]);
        }
    }

    __syncthreads();
#pragma unroll
    for (int k = 0; k < 8; k++) {
        sHo[tt * HS_STRIDE + e0 + k]        = u0[k] + o20[k];
        sHo[(tt + 32) * HS_STRIDE + e0 + k] = u1[k] + o21[k];
    }

    float fo0[8], fo1[8];
#pragma unroll
    for (int k = 0; k < 8; k++) { fo0[k] = bp[e0 + k]; fo1[k] = fo0[k]; }
    for (int dc = 0; dc < 2; dc++) {
        __syncthreads();
#pragma unroll
        for (int i = 0; i < 8; i++) {
            int idx = tid + i * 256;
            int d = idx >> 6, e = idx & 63;
            sW1c[idx] = Wp[(dc * 32 + d) * 64 + e];
        }
        __syncthreads();
#pragma unroll 8
        for (int d = 0; d < 32; d++) {
            float hv0 = sHo[tt * HS_STRIDE + dc * 32 + d];
            float hv1 = sHo[(tt + 32) * HS_STRIDE + dc * 32 + d];
            float4 w0 = *(const float4*)&sW1c[d * 64 + e0];
            float4 w1 = *(const float4*)&sW1c[d * 64 + e0 + 4];
            fo0[0] = fmaf(hv0, w0.x, fo0[0]); fo0[1] = fmaf(hv0, w0.y, fo0[1]);
            fo0[2] = fmaf(hv0, w0.z, fo0[2]); fo0[3] = fmaf(hv0, w0.w, fo0[3]);
            fo0[4] = fmaf(hv0, w1.x, fo0[4]); fo0[5] = fmaf(hv0, w1.y, fo0[5]);
            fo0[6] = fmaf(hv0, w1.z, fo0[6]); fo0[7] = fmaf(hv0, w1.w, fo0[7]);
            fo1[0] = fmaf(hv1, w0.x, fo1[0]); fo1[1] = fmaf(hv1, w0.y, fo1[1]);
            fo1[2] = fmaf(hv1, w0.z, fo1[2]); fo1[3] = fmaf(hv1, w0.w, fo1[3]);
            fo1[4] = fmaf(hv1, w1.x, fo1[4]); fo1[5] = fmaf(hv1, w1.y, fo1[5]);
            fo1[6] = fmaf(hv1, w1.z, fo1[6]); fo1[7] = fmaf(hv1, w1.w, fo1[7]);
        }
    }
#pragma unroll
    for (int k = 0; k < 8; k++) {
        out[tok0 * DH + e0 + k] = fo0[k];
        out[tok1 * DH + e0 + k] = fo1[k];
    }
}

// ---------------- launch ----------------
extern "C" void kernel_launch(void* const* d_in, const int* in_sizes, int n_in,
                              void* d_out, int out_size)
{
    const float* emb    = (const float*)d_in[0];
    const float* Wa     = (const float*)d_in[1];
    const float* ba     = (const float*)d_in[2];
    const float* Wb     = (const float*)d_in[3];
    const float* bb     = (const float*)d_in[4];
    const float* Wc     = (const float*)d_in[5];
    const float* bc     = (const float*)d_in[6];
    const float* head_w = (const float*)d_in[7];
    const float* hn_g   = (const float*)d_in[8];
    const float* hn_b   = (const float*)d_in[9];
    const float* Wd     = (const float*)d_in[10];
    const float* bd     = (const float*)d_in[11];
    const float* W1     = (const float*)d_in[12];
    const float* b1     = (const float*)d_in[13];
    const float* W2     = (const float*)d_in[14];
    const float* b2     = (const float*)d_in[15];
    const float* Wp     = (const float*)d_in[16];
    const float* bp     = (const float*)d_in[17];
    const float* ng     = (const float*)d_in[18];
    const float* nb     = (const float*)d_in[19];
    float* out = (float*)d_out;

    cudaFuncSetAttribute(gemm_tf32_kernel, cudaFuncAttributeMaxDynamicSharedMemorySize, GEMM_SMEM);
    cudaFuncSetAttribute(post_kernel, cudaFuncAttributeMaxDynamicSharedMemorySize, POST_BYTES);

    preround_kernel<<<(int)((size_t)MT * GK / 4 / 256), 256>>>(emb);
    pack_a_kernel<<<4096, 256>>>(Wa);
    pack_bd_kernel<<<4608, 256>>>(Wb, Wd);

    dim3 ggrid(GNP / 128, MT / 256);
    gemm_tf32_kernel<<<ggrid, 256, GEMM_SMEM>>>(ba, bb, bd);

    scanA_kernel<<<BB * SCH, 1024>>>();
    scanC_kernel<<<BB * SCH, 1024>>>();

    post_kernel<<<MT / TOK, 256, POST_BYTES>>>(Wc, bc, head_w, hn_g, hn_b,
                                               W1, b1, W2, b2, Wp, bp, ng, nb, out);
}

// round 10
// speedup vs baseline: 1.0990x; 1.0990x over previous
#include <cuda_runtime.h>
#include <cuda_bf16.h>
#include <math.h>
#include <stdint.h>

// Problem constants
#define EB 1024     // embed dim
#define DH 64       // head dim
#define NH 16       // heads
#define BB 8
#define LL 4096
#define MT (BB*LL)          // 32768 tokens
#define GNP 2176            // padded N (17 tiles of 128)
#define GK EB

// ---------------- scratch ----------------
__device__ float g_a [ (size_t)MT * EB ];
__device__ float g_b [ (size_t)MT * EB ];
__device__ float g_hs[ (size_t)MT * EB ];
__device__ float g_dx[ (size_t)MT * DH ];
__device__ float g_wt[ (size_t)GNP * GK ];  // weights [n][k], tf32-rounded
__device__ float g_et[ (size_t)MT * GK ];   // emb, tf32-rounded

#define SCH 32
#define SCL (LL / SCH)      // 128
__device__ float g_cp[128 * SCH * 64];
__device__ float g_cq[128 * SCH * 64];

// ---------------- helpers ----------------
__device__ __forceinline__ uint32_t smem_u32(const void* p) {
    uint32_t r;
    asm("{ .reg .u64 t; cvta.to.shared.u64 t, %1; cvt.u32.u64 %0, t; }" : "=r"(r) : "l"(p));
    return r;
}
__device__ __forceinline__ void cp_async16(uint32_t dst, const void* src) {
    asm volatile("cp.async.cg.shared.global [%0], [%1], 16;" :: "r"(dst), "l"(src) : "memory");
}
__device__ __forceinline__ void cp_commit() {
    asm volatile("cp.async.commit_group;" ::: "memory");
}
__device__ __forceinline__ uint32_t tf32u(float x) {
    uint32_t u;
    asm("cvt.rna.tf32.f32 %0, %1;" : "=r"(u) : "f"(x));
    return u;
}
__device__ __forceinline__ void mma_tf32(float* c,
                                         uint32_t a0, uint32_t a1, uint32_t a2, uint32_t a3,
                                         uint32_t b0, uint32_t b1) {
    asm volatile(
        "mma.sync.aligned.m16n8k8.row.col.f32.tf32.tf32.f32 "
        "{%0,%1,%2,%3}, {%4,%5,%6,%7}, {%8,%9}, {%0,%1,%2,%3};"
        : "+f"(c[0]), "+f"(c[1]), "+f"(c[2]), "+f"(c[3])
        : "r"(a0), "r"(a1), "r"(a2), "r"(a3), "r"(b0), "r"(b1));
}
__device__ __forceinline__ float tanh_fast(float x) {
    float xc = fminf(fmaxf(x, -10.f), 10.f);
    float t  = __expf(2.f * xc);
    return __fdividef(t - 1.f, t + 1.f);
}

// ---------------- launch 0: pre-round emb to tf32 ----------------
__global__ void preround_kernel(const float* __restrict__ emb)
{
    size_t i = ((size_t)blockIdx.x * 256 + threadIdx.x) * 4;
    float4 x = *(const float4*)(emb + i);
    float4 y;
    y.x = __uint_as_float(tf32u(x.x));
    y.y = __uint_as_float(tf32u(x.y));
    y.z = __uint_as_float(tf32u(x.z));
    y.w = __uint_as_float(tf32u(x.w));
    *(float4*)(g_et + i) = y;
}

// ---------------- launches 1,2: pack weights [n][k] ----------------
__global__ void pack_a_kernel(const float* __restrict__ Wa)
{
    size_t idx = (size_t)blockIdx.x * 256 + threadIdx.x;   // < 1024*1024
    int n = (int)(idx >> 10);
    int k = (int)(idx & 1023);
    float v = Wa[(size_t)(n >> 6) * (EB * DH) + (size_t)k * DH + (n & 63)];
    g_wt[idx] = __uint_as_float(tf32u(v));
}
__global__ void pack_bd_kernel(const float* __restrict__ Wb, const float* __restrict__ Wd)
{
    size_t idx = (size_t)blockIdx.x * 256 + threadIdx.x;   // < 1152*1024
    int n = (int)(idx >> 10);
    int k = (int)(idx & 1023);
    float v;
    if (n < 1024) {
        v = Wb[(size_t)(n >> 6) * (EB * DH) + (size_t)k * DH + (n & 63)];
    } else {
        int n2 = n - 1024;
        v = (n2 < 64) ? Wd[(size_t)k * DH + n2] : 0.f;
    }
    g_wt[(size_t)(1024 + n) * 1024 + k] = __uint_as_float(tf32u(v));
}

// ---------------- launch 3: TF32 gates GEMM, CTA 128x128, warp 32x64 ----------------
#define KC 32
#define NKC (GK / KC)          // 32
#define ROWB 128
#define TILEB (128 * ROWB)     // 16384
#define STAGEB (2 * TILEB)     // A + B = 32768
#define GEMM_SMEM (3 * STAGEB) // 98304 (>= epilogue sD 67584)

#define SWZ(row, chunk) ((uint32_t)((row) * ROWB + ((((chunk) ^ (((row) & 1) << 2))) << 4)))

__device__ __forceinline__ void gemm_load_stage(uint32_t sst, int kc, int tid,
                                                const char* Ag, const char* Bg)
{
    const size_t kb = (size_t)kc * 128;
#pragma unroll
    for (int j = 0; j < 4; j++) {
        int id  = tid + j * 256;
        int row = id >> 3;
        int c   = id & 7;
        cp_async16(sst + SWZ(row, c),         Ag + (size_t)row * 4096 + kb + c * 16);
        cp_async16(sst + TILEB + SWZ(row, c), Bg + (size_t)row * 4096 + kb + c * 16);
    }
}

__global__ void __launch_bounds__(256)
gemm_tf32_kernel(const float* __restrict__ ba,
                 const float* __restrict__ bb,
                 const float* __restrict__ bd)
{
    extern __shared__ char sm_raw[];
    const int tid  = threadIdx.x;
    const int wid  = tid >> 5;
    const int lane = tid & 31;
    const uint32_t sbase = smem_u32(sm_raw);

    const long m0 = (long)blockIdx.y * 128;
    const int  n0 = blockIdx.x * 128;
    const int  wm = (wid & 3) * 32;
    const int  wn = (wid >> 2) * 64;

    const char* Ag = (const char*)(g_et + (size_t)m0 * GK);
    const char* Bg = (const char*)(g_wt + (size_t)n0 * GK);

    float acc[2][8][4];
#pragma unroll
    for (int i = 0; i < 2; i++)
#pragma unroll
        for (int j = 0; j < 8; j++)
#pragma unroll
            for (int q = 0; q < 4; q++) acc[i][j][q] = 0.f;

    gemm_load_stage(sbase, 0, tid, Ag, Bg);
    cp_commit();
    gemm_load_stage(sbase + STAGEB, 1, tid, Ag, Bg);
    cp_commit();

    const int lrow4 = lane >> 2;
    const int lch   = lane & 3;

    int stage = 0;
    for (int kc = 0; kc < NKC; kc++) {
        if (kc + 1 < NKC) {
            asm volatile("cp.async.wait_group 1;" ::: "memory");
        } else {
            asm volatile("cp.async.wait_group 0;" ::: "memory");
        }
        __syncthreads();
        if (kc + 2 < NKC) {
            int nstage = stage + 2; if (nstage >= 3) nstage -= 3;
            gemm_load_stage(sbase + nstage * STAGEB, kc + 2, tid, Ag, Bg);
            cp_commit();
        }

        const char* sA = sm_raw + stage * STAGEB;
        const char* sB = sA + TILEB;

#pragma unroll
        for (int k16 = 0; k16 < 2; k16++) {
            const int ch = k16 * 4 + lch;
            uint32_t aw[2][2][4];
#pragma unroll
            for (int mt = 0; mt < 2; mt++) {
#pragma unroll
                for (int hh = 0; hh < 2; hh++) {
                    int row = wm + mt * 16 + hh * 8 + lrow4;
                    const uint4 v = *(const uint4*)(sA + SWZ(row, ch));
                    aw[mt][hh][0] = v.x;
                    aw[mt][hh][1] = v.y;
                    aw[mt][hh][2] = v.z;
                    aw[mt][hh][3] = v.w;
                }
            }
#pragma unroll
            for (int g = 0; g < 8; g++) {
                int row = wn + g * 8 + lrow4;
                const uint4 bv = *(const uint4*)(sB + SWZ(row, ch));
                mma_tf32(acc[0][g], aw[0][0][0], aw[0][1][0], aw[0][0][1], aw[0][1][1], bv.x, bv.y);
                mma_tf32(acc[0][g], aw[0][0][2], aw[0][1][2], aw[0][0][3], aw[0][1][3], bv.z, bv.w);
                mma_tf32(acc[1][g], aw[1][0][0], aw[1][1][0], aw[1][0][1], aw[1][1][1], bv.x, bv.y);
                mma_tf32(acc[1][g], aw[1][0][2], aw[1][1][2], aw[1][0][3], aw[1][1][3], bv.z, bv.w);
            }
        }
        stage++; if (stage == 3) stage = 0;
    }
    __syncthreads();

    // ---- epilogue ----
    float* sD = (float*)sm_raw;   // 128 x 132
#pragma unroll
    for (int mt = 0; mt < 2; mt++) {
#pragma unroll
        for (int g = 0; g < 8; g++) {
            int ml = wm + mt * 16 + (lane >> 2);
            int nl = wn + g * 8 + (lane & 3) * 2;
            *(float2*)&sD[ml * 132 + nl]       = make_float2(acc[mt][g][0], acc[mt][g][1]);
            *(float2*)&sD[(ml + 8) * 132 + nl] = make_float2(acc[mt][g][2], acc[mt][g][3]);
        }
    }
    __syncthreads();

    for (int i = tid; i < 128 * 128; i += 256) {
        int mm = i >> 7;
        int nn = i & 127;
        int ng = n0 + nn;
        float c = sD[mm * 132 + nn];
        long m = m0 + mm;
        if (ng < 1024) {
            g_a[m * EB + ng] = tanh_fast(c + ba[ng]);
        } else if (ng < 2048) {
            g_b[m * EB + (ng - 1024)] = c + bb[ng - 1024];
        } else if (ng < 2112) {
            g_dx[m * DH + (ng - 2048)] = c + bd[ng - 2048];
        }
    }
}

// ---------------- chunked scan ----------------
__global__ void __launch_bounds__(1024)
scanA_kernel()
{
    const int b = blockIdx.x >> 5;
    const int c = blockIdx.x & 31;
    const int e = threadIdx.x;
    size_t base = ((size_t)b * LL + (size_t)c * SCL) * EB + e;
    float P = 1.f, Q = 0.f;
#pragma unroll 8
    for (int l = 0; l < SCL; l++) {
        size_t idx = base + (size_t)l * EB;
        float av = g_a[idx];
        float bv = g_b[idx];
        Q = fmaf(av, Q, bv);
        P *= av;
    }
    int bh = b * 16 + (e >> 6);
    g_cp[(bh * SCH + c) * 64 + (e & 63)] = P;
    g_cq[(bh * SCH + c) * 64 + (e & 63)] = Q;
}

__global__ void __launch_bounds__(1024)
scanC_kernel()
{
    const int b = blockIdx.x >> 5;
    const int c = blockIdx.x & 31;
    const int e = threadIdx.x;
    const int bh = b * 16 + (e >> 6);
    const int d  = e & 63;
    float hv = 0.f;
    for (int cc = 0; cc < c; cc++) {
        int i = (bh * SCH + cc) * 64 + d;
        hv = fmaf(g_cp[i], hv, g_cq[i]);
    }
    size_t base = ((size_t)b * LL + (size_t)c * SCL) * EB + e;
#pragma unroll 8
    for (int l = 0; l < SCL; l++) {
        size_t idx = base + (size_t)l * EB;
        float av = g_a[idx];
        float bv = g_b[idx];
        hv = fmaf(av, hv, bv);
        g_hs[idx] = hv;
    }
}

// ---------------- fused per-token epilogue ----------------
#define TOK 64
#define HS_STRIDE 68
#define POST_FLOATS 21248
#define POST_BYTES  (POST_FLOATS * 4)

__device__ __forceinline__ float grp8_sum(float v) {
    v += __shfl_xor_sync(0xffffffffu, v, 1);
    v += __shfl_xor_sync(0xffffffffu, v, 2);
    v += __shfl_xor_sync(0xffffffffu, v, 4);
    return v;
}

__device__ __forceinline__ void post_prefetch(uint32_t swc, uint32_t shs,
                                              const float* __restrict__ Wc,
                                              int h, long token0, int tid)
{
    const char* wsrc = (const char*)(Wc + (size_t)h * 4096);
#pragma unroll
    for (int i = 0; i < 4; i++) {
        int idx = tid + i * 256;
        cp_async16(swc + idx * 16, wsrc + idx * 16);
    }
#pragma unroll
    for (int i = 0; i < 4; i++) {
        int idx = tid + i * 256;
        int t = idx >> 4;
        int c = idx & 15;
        const char* hsrc = (const char*)(g_hs + (token0 + t) * (size_t)EB + h * 64);
        cp_async16(shs + (uint32_t)(t * HS_STRIDE * 4 + c * 16), hsrc + c * 16);
    }
}

__global__ void __launch_bounds__(256)
post_kernel(const float* __restrict__ Wc,  const float* __restrict__ bc,
            const float* __restrict__ head_w,
            const float* __restrict__ hn_g, const float* __restrict__ hn_b,
            const float* __restrict__ W1,  const float* __restrict__ b1,
            const float* __restrict__ W2,  const float* __restrict__ b2,
            const float* __restrict__ Wp,  const float* __restrict__ bp,
            const float* __restrict__ ng,  const float* __restrict__ nb,
            float* __restrict__ out)
{
    extern __shared__ float sm[];
    const int tid = threadIdx.x;
    const int tt  = tid >> 3;
    const int eg  = tid & 7;
    const int e0  = eg * 8;
    const long token0 = (long)blockIdx.x * TOK;
    const long tok0 = token0 + tt;
    const long tok1 = token0 + tt + 32;

    const uint32_t swc_u0 = smem_u32(sm);
    const uint32_t swc_u1 = smem_u32(sm + 4096);
    const uint32_t shs_u0 = smem_u32(sm + 8192);
    const uint32_t shs_u1 = smem_u32(sm + 8192 + TOK * HS_STRIDE);

    float dxv0[8], dxv1[8], acc0[8], acc1[8];
#pragma unroll
    for (int k = 0; k < 8; k++) {
        dxv0[k] = g_dx[tok0 * DH + e0 + k];
        dxv1[k] = g_dx[tok1 * DH + e0 + k];
        acc0[k] = dxv0[k];
        acc1[k] = dxv1[k];
    }

    post_prefetch(swc_u0, shs_u0, Wc, 0, token0, tid);
    cp_commit();

    for (int h = 0; h < NH; h++) {
        const int cur = h & 1;
        if (h + 1 < NH) {
            post_prefetch(cur ? swc_u0 : swc_u1, cur ? shs_u0 : shs_u1, Wc, h + 1, token0, tid);
            cp_commit();
            asm volatile("cp.async.wait_group 1;" ::: "memory");
        } else {
            asm volatile("cp.async.wait_group 0;" ::: "memory");
        }
        __syncthreads();

        const float* sWc = sm + (cur ? 4096 : 0);
        const float* sHs = sm + 8192 + (cur ? TOK * HS_STRIDE : 0);

        float o0[8], o1[8];
#pragma unroll
        for (int k = 0; k < 8; k++) {
            float bck = bc[h * DH + e0 + k];
            o0[k] = bck + dxv0[k];
            o1[k] = bck + dxv1[k];
        }
#pragma unroll 8
        for (int d = 0; d < 64; d++) {
            float hv0 = sHs[tt * HS_STRIDE + d];
            float hv1 = sHs[(tt + 32) * HS_STRIDE + d];
            float4 w0 = *(const float4*)&sWc[d * 64 + e0];
            float4 w1 = *(const float4*)&sWc[d * 64 + e0 + 4];
            o0[0] = fmaf(hv0, w0.x, o0[0]); o0[1] = fmaf(hv0, w0.y, o0[1]);
            o0[2] = fmaf(hv0, w0.z, o0[2]); o0[3] = fmaf(hv0, w0.w, o0[3]);
            o0[4] = fmaf(hv0, w1.x, o0[4]); o0[5] = fmaf(hv0, w1.y, o0[5]);
            o0[6] = fmaf(hv0, w1.z, o0[6]); o0[7] = fmaf(hv0, w1.w, o0[7]);
            o1[0] = fmaf(hv1, w0.x, o1[0]); o1[1] = fmaf(hv1, w0.y, o1[1]);
            o1[2] = fmaf(hv1, w0.z, o1[2]); o1[3] = fmaf(hv1, w0.w, o1[3]);
            o1[4] = fmaf(hv1, w1.x, o1[4]); o1[5] = fmaf(hv1, w1.y, o1[5]);
            o1[6] = fmaf(hv1, w1.z, o1[6]); o1[7] = fmaf(hv1, w1.w, o1[7]);
        }
        float s10 = 0.f, s20 = 0.f, s11 = 0.f, s21 = 0.f;
#pragma unroll
        for (int k = 0; k < 8; k++) {
            s10 += o0[k]; s20 += o0[k] * o0[k];
            s11 += o1[k]; s21 += o1[k] * o1[k];
        }
        s10 = grp8_sum(s10); s20 = grp8_sum(s20);
        s11 = grp8_sum(s11); s21 = grp8_sum(s21);
        float mean0 = s10 * (1.f / 64.f);
        float var0  = s20 * (1.f / 64.f) - mean0 * mean0;
        float rstd0 = rsqrtf(var0 + 1e-5f);
        float mean1 = s11 * (1.f / 64.f);
        float var1  = s21 * (1.f / 64.f) - mean1 * mean1;
        float rstd1 = rsqrtf(var1 + 1e-5f);
        float hw = head_w[h];
#pragma unroll
        for (int k = 0; k < 8; k++) {
            float gk = hn_g[h * DH + e0 + k];
            float bk = hn_b[h * DH + e0 + k];
            acc0[k] = fmaf(hw, (o0[k] - mean0) * rstd0 * gk + bk, acc0[k]);
            acc1[k] = fmaf(hw, (o1[k] - mean1) * rstd1 * gk + bk, acc1[k]);
        }
        __syncthreads();
    }

    float u0[8], u1[8];
    {
        float s10 = 0.f, s20 = 0.f, s11 = 0.f, s21 = 0.f;
#pragma unroll
        for (int k = 0; k < 8; k++) {
            acc0[k] *= (1.f / (float)NH);
            acc1[k] *= (1.f / (float)NH);
            s10 += acc0[k]; s20 += acc0[k] * acc0[k];
            s11 += acc1[k]; s21 += acc1[k] * acc1[k];
        }
        s10 = grp8_sum(s10); s20 = grp8_sum(s20);
        s11 = grp8_sum(s11); s21 = grp8_sum(s21);
        float mean0 = s10 * (1.f / 64.f);
        float var0  = s20 * (1.f / 64.f) - mean0 * mean0;
        float rstd0 = rsqrtf(var0 + 1e-5f);
        float mean1 = s11 * (1.f / 64.f);
        float var1  = s21 * (1.f / 64.f) - mean1 * mean1;
        float rstd1 = rsqrtf(var1 + 1e-5f);
#pragma unroll
        for (int k = 0; k < 8; k++) {
            float ngk = ng[e0 + k], nbk = nb[e0 + k];
            u0[k] = acc0[k] + (acc0[k] - mean0) * rstd0 * ngk + nbk;
            u1[k] = acc1[k] + (acc1[k] - mean1) * rstd1 * ngk + nbk;
        }
    }

    __syncthreads();

    float* sW1c = sm;
    float* sW2c = sm + 4096;
    float* sU   = sm + 8192;
    float* sGc  = sm + 8192 + TOK * HS_STRIDE;
    float* sHo  = sm + 8192 + 2 * TOK * HS_STRIDE;

#pragma unroll
    for (int k = 0; k < 8; k++) {
        sU[tt * HS_STRIDE + e0 + k]        = u0[k];
        sU[(tt + 32) * HS_STRIDE + e0 + k] = u1[k];
    }

    float o20[8], o21[8];
#pragma unroll
    for (int k = 0; k < 8; k++) { o20[k] = b2[e0 + k]; o21[k] = o20[k]; }

    for (int jc = 0; jc < 4; jc++) {
        __syncthreads();
#pragma unroll
        for (int i = 0; i < 16; i++) {
            int idx = tid + i * 256;
            int d = idx >> 6, jj = idx & 63;
            sW1c[idx] = W1[d * 256 + jc * 64 + jj];
            sW2c[idx] = W2[(jc * 64 + (idx >> 6)) * 64 + (idx & 63)];
        }
        __syncthreads();
#pragma unroll
        for (int kk = 0; kk < 8; kk++) {
            int jl = eg + 8 * kk;
            float m0 = b1[jc * 64 + jl], m1 = m0;
#pragma unroll 8
            for (int d = 0; d < 64; d++) {
                float w = sW1c[d * 64 + jl];
                m0 = fmaf(sU[tt * HS_STRIDE + d], w, m0);
                m1 = fmaf(sU[(tt + 32) * HS_STRIDE + d], w, m1);
            }
            sGc[tt * HS_STRIDE + jl]        = 0.5f * m0 * (1.f + erff(m0 * 0.70710678118654752f));
            sGc[(tt + 32) * HS_STRIDE + jl] = 0.5f * m1 * (1.f + erff(m1 * 0.70710678118654752f));
        }
        __syncthreads();
#pragma unroll 8
        for (int jj = 0; jj < 64; jj++) {
            float gv0 = sGc[tt * HS_STRIDE + jj];
            float gv1 = sGc[(tt + 32) * HS_STRIDE + jj];
            float4 w0 = *(const float4*)&sW2c[jj * 64 + e0];
            float4 w1 = *(const float4*)&sW2c[jj * 64 + e0 + 4];
            o20[0] = fmaf(gv0, w0.x, o20[0]); o20[1] = fmaf(gv0, w0.y, o20[1]);
            o20[2] = fmaf(gv0, w0.z, o20[2]); o20[3] = fmaf(gv0, w0.w, o20[3]);
            o20[4] = fmaf(gv0, w1.x, o20[4]); o20[5] = fmaf(gv0, w1.y, o20[5]);
            o20[6] = fmaf(gv0, w1.z, o20[6]); o20[7] = fmaf(gv0, w1.w, o20[7]);
            o21[0] = fmaf(gv1, w0.x, o21[0]); o21[1] = fmaf(gv1, w0.y, o21[1]);
            o21[2] = fmaf(gv1, w0.z, o21[2]); o21[3] = fmaf(gv1, w0.w, o21[3]);
            o21[4] = fmaf(gv1, w1.x, o21[4]); o21[5] = fmaf(gv1, w1.y, o21[5]);
            o21[6] = fmaf(gv1, w1.z, o21[6]); o21[7] = fmaf(gv1, w1.w, o21[7]);
        }
    }

    __syncthreads();
#pragma unroll
    for (int k = 0; k < 8; k++) {
        sHo[tt * HS_STRIDE + e0 + k]        = u0[k] + o20[k];
        sHo[(tt + 32) * HS_STRIDE + e0 + k] = u1[k] + o21[k];
    }

    float fo0[8], fo1[8];
#pragma unroll
    for (int k = 0; k < 8; k++) { fo0[k] = bp[e0 + k]; fo1[k] = fo0[k]; }
    for (int dc = 0; dc < 2; dc++) {
        __syncthreads();
#pragma unroll
        for (int i = 0; i < 8; i++) {
            int idx = tid + i * 256;
            int d = idx >> 6, e = idx & 63;
            sW1c[idx] = Wp[(dc * 32 + d) * 64 + e];
        }
        __syncthreads();
#pragma unroll 8
        for (int d = 0; d < 32; d++) {
            float hv0 = sHo[tt * HS_STRIDE + dc * 32 + d];
            float hv1 = sHo[(tt + 32) * HS_STRIDE + dc * 32 + d];
            float4 w0 = *(const float4*)&sW1c[d * 64 + e0];
            float4 w1 = *(const float4*)&sW1c[d * 64 + e0 + 4];
            fo0[0] = fmaf(hv0, w0.x, fo0[0]); fo0[1] = fmaf(hv0, w0.y, fo0[1]);
            fo0[2] = fmaf(hv0, w0.z, fo0[2]); fo0[3] = fmaf(hv0, w0.w, fo0[3]);
            fo0[4] = fmaf(hv0, w1.x, fo0[4]); fo0[5] = fmaf(hv0, w1.y, fo0[5]);
            fo0[6] = fmaf(hv0, w1.z, fo0[6]); fo0[7] = fmaf(hv0, w1.w, fo0[7]);
            fo1[0] = fmaf(hv1, w0.x, fo1[0]); fo1[1] = fmaf(hv1, w0.y, fo1[1]);
            fo1[2] = fmaf(hv1, w0.z, fo1[2]); fo1[3] = fmaf(hv1, w0.w, fo1[3]);
            fo1[4] = fmaf(hv1, w1.x, fo1[4]); fo1[5] = fmaf(hv1, w1.y, fo1[5]);
            fo1[6] = fmaf(hv1, w1.z, fo1[6]); fo1[7] = fmaf(hv1, w1.w, fo1[7]);
        }
    }
#pragma unroll
    for (int k = 0; k < 8; k++) {
        out[tok0 * DH + e0 + k] = fo0[k];
        out[tok1 * DH + e0 + k] = fo1[k];
    }
}

// ---------------- launch ----------------
extern "C" void kernel_launch(void* const* d_in, const int* in_sizes, int n_in,
                              void* d_out, int out_size)
{
    const float* emb    = (const float*)d_in[0];
    const float* Wa     = (const float*)d_in[1];
    const float* ba     = (const float*)d_in[2];
    const float* Wb     = (const float*)d_in[3];
    const float* bb     = (const float*)d_in[4];
    const float* Wc     = (const float*)d_in[5];
    const float* bc     = (const float*)d_in[6];
    const float* head_w = (const float*)d_in[7];
    const float* hn_g   = (const float*)d_in[8];
    const float* hn_b   = (const float*)d_in[9];
    const float* Wd     = (const float*)d_in[10];
    const float* bd     = (const float*)d_in[11];
    const float* W1     = (const float*)d_in[12];
    const float* b1     = (const float*)d_in[13];
    const float* W2     = (const float*)d_in[14];
    const float* b2     = (const float*)d_in[15];
    const float* Wp     = (const float*)d_in[16];
    const float* bp     = (const float*)d_in[17];
    const float* ng     = (const float*)d_in[18];
    const float* nb     = (const float*)d_in[19];
    float* out = (float*)d_out;

    cudaFuncSetAttribute(gemm_tf32_kernel, cudaFuncAttributeMaxDynamicSharedMemorySize, GEMM_SMEM);
    cudaFuncSetAttribute(post_kernel, cudaFuncAttributeMaxDynamicSharedMemorySize, POST_BYTES);

    preround_kernel<<<(int)((size_t)MT * GK / 4 / 256), 256>>>(emb);
    pack_a_kernel<<<4096, 256>>>(Wa);
    pack_bd_kernel<<<4608, 256>>>(Wb, Wd);

    dim3 ggrid(GNP / 128, MT / 128);
    gemm_tf32_kernel<<<ggrid, 256, GEMM_SMEM>>>(ba, bb, bd);

    scanA_kernel<<<BB * SCH, 1024>>>();
    scanC_kernel<<<BB * SCH, 1024>>>();

    post_kernel<<<MT / TOK, 256, POST_BYTES>>>(Wc, bc, head_w, hn_g, hn_b,
                                               W1, b1, W2, b2, Wp, bp, ng, nb, out);
}